// round 5
// baseline (speedup 1.0000x reference)
#include <cuda_runtime.h>
#include <math.h>

#define BATCH 32
#define SEQ 4096
#define HIDDEN 2048
#define ROUTE_H 256
#define NUM_EXPERTS 64
#define TOP_K 8
#define LN_EPS 1e-5f

#define NSPLIT 32
#define SCHUNK (SEQ / NSPLIT)        // 128 rows per block
#define H4 (HIDDEN / 4)              // 512 float4 columns

#define KB 8                         // K-split blocks for GEMV1
#define KCHUNK (HIDDEN / KB)         // 256 hidden cols per GEMV1 block

// Scratch (no cudaMalloc allowed)
__device__ float g_partial[NSPLIT * BATCH * HIDDEN];   // [sp][b][h] = 8 MB
__device__ float g_hpart[KB * BATCH * ROUTE_H];        // [ks][b][j] = 256 KB

// ---------------------------------------------------------------------------
// Kernel 1: partial mean-pool. grid = BATCH*NSPLIT = 1024 blocks, 512 threads.
// Each thread accumulates one float4 column over its 128-row seq slice.
// Streaming loads (__ldcs): the 1 GB input is touched once; keep it out of L2.
// ---------------------------------------------------------------------------
__global__ void __launch_bounds__(512) pool_partial(const float* __restrict__ x) {
    int blk = blockIdx.x;
    int b   = blk / NSPLIT;
    int sp  = blk % NSPLIT;
    int c4  = threadIdx.x;  // 0..511

    const float4* base = (const float4*)(x) +
        ((size_t)b * SEQ + (size_t)sp * SCHUNK) * (size_t)H4 + c4;

    float4 acc = make_float4(0.f, 0.f, 0.f, 0.f);
#pragma unroll 8
    for (int s = 0; s < SCHUNK; s++) {
        float4 v = __ldcs(&base[(size_t)s * H4]);
        acc.x += v.x; acc.y += v.y; acc.z += v.z; acc.w += v.w;
    }

    float4* out = (float4*)(g_partial + ((size_t)sp * BATCH + b) * HIDDEN);
    out[c4] = acc;
}

// ---------------------------------------------------------------------------
// Kernel 2: GEMV1 K-split across the grid. grid = BATCH*KB = 256 blocks,
// 256 threads. Block (b, ks): fold pooled cols [ks*256, ks*256+256), then
// partial h[j] = sum over those 256 rows of pooled[r] * W1[r][j].
// ---------------------------------------------------------------------------
__global__ void __launch_bounds__(ROUTE_H) gemv1_partial(
    const float* __restrict__ W1)
{
    __shared__ float sh_pool[KCHUNK];

    int blk = blockIdx.x;
    int b   = blk / KB;
    int ks  = blk % KB;
    int j   = threadIdx.x;           // 0..255
    int i0  = ks * KCHUNK;

    // Fold NSPLIT partials for this block's 256 pooled columns.
    // Thread j owns column i0+j: 32 loads, coalesced across threads.
    {
        float s = 0.f;
#pragma unroll
        for (int sp = 0; sp < NSPLIT; sp++)
            s += g_partial[((size_t)sp * BATCH + b) * HIDDEN + i0 + j];
        sh_pool[j] = s * (1.0f / SEQ);
    }
    __syncthreads();

    // Partial GEMV over 256 rows (coalesced W1 reads across j).
    float a0 = 0.f, a1 = 0.f, a2 = 0.f, a3 = 0.f;
    float a4 = 0.f, a5 = 0.f, a6 = 0.f, a7 = 0.f;
#pragma unroll 4
    for (int r = 0; r < KCHUNK; r += 8) {
        const float* w = W1 + (size_t)(i0 + r) * ROUTE_H + j;
        a0 += sh_pool[r + 0] * w[0 * ROUTE_H];
        a1 += sh_pool[r + 1] * w[1 * ROUTE_H];
        a2 += sh_pool[r + 2] * w[2 * ROUTE_H];
        a3 += sh_pool[r + 3] * w[3 * ROUTE_H];
        a4 += sh_pool[r + 4] * w[4 * ROUTE_H];
        a5 += sh_pool[r + 5] * w[5 * ROUTE_H];
        a6 += sh_pool[r + 6] * w[6 * ROUTE_H];
        a7 += sh_pool[r + 7] * w[7 * ROUTE_H];
    }
    float acc = ((a0 + a1) + (a2 + a3)) + ((a4 + a5) + (a6 + a7));

    g_hpart[((size_t)ks * BATCH + b) * ROUTE_H + j] = acc;
}

// ---------------------------------------------------------------------------
// Kernel 3: finale. grid = BATCH blocks, 256 threads.
// Fold KB h-partials + b1, LN, GELU, GEMV2, top-8 softmax scatter.
// ---------------------------------------------------------------------------
__global__ void __launch_bounds__(ROUTE_H) finale(
    const float* __restrict__ b1,
    const float* __restrict__ ln_g, const float* __restrict__ ln_b,
    const float* __restrict__ W2, const float* __restrict__ b2,
    float* __restrict__ out)
{
    __shared__ float sh_h[ROUTE_H];
    __shared__ float sh_w1[8], sh_w2[8];
    __shared__ float sh_part[ROUTE_H];
    __shared__ float sh_logits[NUM_EXPERTS];

    int b = blockIdx.x;
    int j = threadIdx.x;
    int lane = j & 31;
    int warp = j >> 5;

    // Fold KB partials
    float h = 0.f;
#pragma unroll
    for (int ks = 0; ks < KB; ks++)
        h += g_hpart[((size_t)ks * BATCH + b) * ROUTE_H + j];
    h += b1[j];

    // LN reduce via warp shuffles (8 warps)
    float s1 = h, s2 = h * h;
#pragma unroll
    for (int o = 16; o > 0; o >>= 1) {
        s1 += __shfl_xor_sync(0xffffffffu, s1, o);
        s2 += __shfl_xor_sync(0xffffffffu, s2, o);
    }
    if (lane == 0) { sh_w1[warp] = s1; sh_w2[warp] = s2; }
    __syncthreads();
    float t1 = sh_w1[lane & 7], t2 = sh_w2[lane & 7];
#pragma unroll
    for (int o = 4; o > 0; o >>= 1) {
        t1 += __shfl_xor_sync(0xffffffffu, t1, o);
        t2 += __shfl_xor_sync(0xffffffffu, t2, o);
    }
    t1 = __shfl_sync(0xffffffffu, t1, 0);
    t2 = __shfl_sync(0xffffffffu, t2, 0);

    float mu  = t1 * (1.0f / ROUTE_H);
    float ms  = t2 * (1.0f / ROUTE_H);
    float inv = rsqrtf(ms - mu * mu + LN_EPS);
    h = (h - mu) * inv * ln_g[j] + ln_b[j];
    // exact GELU
    h = 0.5f * h * (1.0f + erff(h * 0.70710678118654752f));
    sh_h[j] = h;
    __syncthreads();

    // GEMV2, K-split 4 within the block: 256 threads = 64 experts x 4 slices
    {
        int e   = j & (NUM_EXPERTS - 1);
        int ks2 = j >> 6;
        int r0  = ks2 * (ROUTE_H / 4);
        float a = 0.f;
#pragma unroll 8
        for (int i = 0; i < ROUTE_H / 4; i++)
            a += sh_h[r0 + i] * W2[(size_t)(r0 + i) * NUM_EXPERTS + e];
        sh_part[j] = a;
    }
    __syncthreads();
    if (j < NUM_EXPERTS) {
        sh_logits[j] = ((sh_part[j] + sh_part[j + 64]) +
                        (sh_part[j + 128] + sh_part[j + 192])) + b2[j];
        out[(size_t)b * NUM_EXPERTS + j] = 0.0f;   // d_out poisoned; zero first
    }
    __syncthreads();

    // top-8 + softmax + scatter (strict '>' = first-index tie-break, as
    // jax.lax.top_k)
    if (j == 0) {
        int   idx[TOP_K];
        float val[TOP_K];
        unsigned long long used = 0ull;
        for (int k = 0; k < TOP_K; k++) {
            float best = -INFINITY;
            int bi = 0;
            for (int e = 0; e < NUM_EXPERTS; e++) {
                if (!((used >> e) & 1ull) && sh_logits[e] > best) {
                    best = sh_logits[e]; bi = e;
                }
            }
            used |= (1ull << bi);
            idx[k] = bi;
            val[k] = best;
        }
        float mx = val[0];
        float denom = 0.f;
        float ex[TOP_K];
        for (int k = 0; k < TOP_K; k++) { ex[k] = expf(val[k] - mx); denom += ex[k]; }
        float rden = 1.0f / denom;
        for (int k = 0; k < TOP_K; k++)
            out[(size_t)b * NUM_EXPERTS + idx[k]] = ex[k] * rden;
    }
}

// ---------------------------------------------------------------------------
extern "C" void kernel_launch(void* const* d_in, const int* in_sizes, int n_in,
                              void* d_out, int out_size) {
    const float* hs   = (const float*)d_in[0];
    const float* W1   = (const float*)d_in[1];
    const float* b1   = (const float*)d_in[2];
    const float* ln_g = (const float*)d_in[3];
    const float* ln_b = (const float*)d_in[4];
    const float* W2   = (const float*)d_in[5];
    const float* b2   = (const float*)d_in[6];
    // d_in[7] = top_k (hardcoded 8)

    float* out = (float*)d_out;

    pool_partial<<<BATCH * NSPLIT, 512>>>(hs);
    gemv1_partial<<<BATCH * KB, ROUTE_H>>>(W1);
    finale<<<BATCH, ROUTE_H>>>(b1, ln_g, ln_b, W2, b2, out);
}

// round 6
// speedup vs baseline: 1.0087x; 1.0087x over previous
#include <cuda_runtime.h>
#include <math.h>

#define BATCH 32
#define SEQ 4096
#define HIDDEN 2048
#define ROUTE_H 256
#define NUM_EXPERTS 64
#define TOP_K 8
#define LN_EPS 1e-5f

#define NSPLIT 32
#define SCHUNK (SEQ / NSPLIT)        // 128 rows per block
#define H4 (HIDDEN / 4)              // 512 float4 columns

#define KB 8                         // K-split blocks for GEMV1
#define KCHUNK (HIDDEN / KB)         // 256 hidden cols per GEMV1 block

// Scratch (no cudaMalloc allowed)
__device__ float g_partial[NSPLIT * BATCH * HIDDEN];   // [sp][b][h] = 8 MB
__device__ float g_hpart[KB * BATCH * ROUTE_H];        // [ks][b][j] = 256 KB

// ---------------------------------------------------------------------------
// Kernel 1: partial mean-pool. grid = BATCH*NSPLIT = 1024 blocks, 512 threads.
// Each thread accumulates one float4 column over its 128-row seq slice.
// Streaming loads (__ldcs): the 1 GB input is touched once; keep it out of L2.
// ---------------------------------------------------------------------------
__global__ void __launch_bounds__(512) pool_partial(const float* __restrict__ x) {
    int blk = blockIdx.x;
    int b   = blk / NSPLIT;
    int sp  = blk % NSPLIT;
    int c4  = threadIdx.x;  // 0..511

    const float4* base = (const float4*)(x) +
        ((size_t)b * SEQ + (size_t)sp * SCHUNK) * (size_t)H4 + c4;

    float4 acc = make_float4(0.f, 0.f, 0.f, 0.f);
#pragma unroll 8
    for (int s = 0; s < SCHUNK; s++) {
        float4 v = __ldcs(&base[(size_t)s * H4]);
        acc.x += v.x; acc.y += v.y; acc.z += v.z; acc.w += v.w;
    }

    float4* out = (float4*)(g_partial + ((size_t)sp * BATCH + b) * HIDDEN);
    out[c4] = acc;
}

// ---------------------------------------------------------------------------
// Kernel 2: GEMV1 K-split across the grid. grid = BATCH*KB = 256 blocks,
// 256 threads. Block (b, ks): fold pooled cols [ks*256, ks*256+256), then
// partial h[j] = sum over those 256 rows of pooled[r] * W1[r][j].
// ---------------------------------------------------------------------------
__global__ void __launch_bounds__(ROUTE_H) gemv1_partial(
    const float* __restrict__ W1)
{
    __shared__ float sh_pool[KCHUNK];

    int blk = blockIdx.x;
    int b   = blk / KB;
    int ks  = blk % KB;
    int j   = threadIdx.x;           // 0..255
    int i0  = ks * KCHUNK;

    // Fold NSPLIT partials for this block's 256 pooled columns.
    // Thread j owns column i0+j: 32 loads, coalesced across threads.
    {
        float s = 0.f;
#pragma unroll
        for (int sp = 0; sp < NSPLIT; sp++)
            s += g_partial[((size_t)sp * BATCH + b) * HIDDEN + i0 + j];
        sh_pool[j] = s * (1.0f / SEQ);
    }
    __syncthreads();

    // Partial GEMV over 256 rows (coalesced W1 reads across j).
    float a0 = 0.f, a1 = 0.f, a2 = 0.f, a3 = 0.f;
    float a4 = 0.f, a5 = 0.f, a6 = 0.f, a7 = 0.f;
#pragma unroll 4
    for (int r = 0; r < KCHUNK; r += 8) {
        const float* w = W1 + (size_t)(i0 + r) * ROUTE_H + j;
        a0 += sh_pool[r + 0] * w[0 * ROUTE_H];
        a1 += sh_pool[r + 1] * w[1 * ROUTE_H];
        a2 += sh_pool[r + 2] * w[2 * ROUTE_H];
        a3 += sh_pool[r + 3] * w[3 * ROUTE_H];
        a4 += sh_pool[r + 4] * w[4 * ROUTE_H];
        a5 += sh_pool[r + 5] * w[5 * ROUTE_H];
        a6 += sh_pool[r + 6] * w[6 * ROUTE_H];
        a7 += sh_pool[r + 7] * w[7 * ROUTE_H];
    }
    float acc = ((a0 + a1) + (a2 + a3)) + ((a4 + a5) + (a6 + a7));

    g_hpart[((size_t)ks * BATCH + b) * ROUTE_H + j] = acc;
}

// ---------------------------------------------------------------------------
// Kernel 3: finale. grid = BATCH blocks, 256 threads.
// Fold KB h-partials + b1, LN, GELU, GEMV2, top-8 softmax scatter.
// ---------------------------------------------------------------------------
__global__ void __launch_bounds__(ROUTE_H) finale(
    const float* __restrict__ b1,
    const float* __restrict__ ln_g, const float* __restrict__ ln_b,
    const float* __restrict__ W2, const float* __restrict__ b2,
    float* __restrict__ out)
{
    __shared__ float sh_h[ROUTE_H];
    __shared__ float sh_w1[8], sh_w2[8];
    __shared__ float sh_part[ROUTE_H];
    __shared__ float sh_logits[NUM_EXPERTS];

    int b = blockIdx.x;
    int j = threadIdx.x;
    int lane = j & 31;
    int warp = j >> 5;

    // Fold KB partials
    float h = 0.f;
#pragma unroll
    for (int ks = 0; ks < KB; ks++)
        h += g_hpart[((size_t)ks * BATCH + b) * ROUTE_H + j];
    h += b1[j];

    // LN reduce via warp shuffles (8 warps)
    float s1 = h, s2 = h * h;
#pragma unroll
    for (int o = 16; o > 0; o >>= 1) {
        s1 += __shfl_xor_sync(0xffffffffu, s1, o);
        s2 += __shfl_xor_sync(0xffffffffu, s2, o);
    }
    if (lane == 0) { sh_w1[warp] = s1; sh_w2[warp] = s2; }
    __syncthreads();
    float t1 = sh_w1[lane & 7], t2 = sh_w2[lane & 7];
#pragma unroll
    for (int o = 4; o > 0; o >>= 1) {
        t1 += __shfl_xor_sync(0xffffffffu, t1, o);
        t2 += __shfl_xor_sync(0xffffffffu, t2, o);
    }
    t1 = __shfl_sync(0xffffffffu, t1, 0);
    t2 = __shfl_sync(0xffffffffu, t2, 0);

    float mu  = t1 * (1.0f / ROUTE_H);
    float ms  = t2 * (1.0f / ROUTE_H);
    float inv = rsqrtf(ms - mu * mu + LN_EPS);
    h = (h - mu) * inv * ln_g[j] + ln_b[j];
    // exact GELU
    h = 0.5f * h * (1.0f + erff(h * 0.70710678118654752f));
    sh_h[j] = h;
    __syncthreads();

    // GEMV2, K-split 4 within the block: 256 threads = 64 experts x 4 slices
    {
        int e   = j & (NUM_EXPERTS - 1);
        int ks2 = j >> 6;
        int r0  = ks2 * (ROUTE_H / 4);
        float a = 0.f;
#pragma unroll 8
        for (int i = 0; i < ROUTE_H / 4; i++)
            a += sh_h[r0 + i] * W2[(size_t)(r0 + i) * NUM_EXPERTS + e];
        sh_part[j] = a;
    }
    __syncthreads();
    if (j < NUM_EXPERTS) {
        sh_logits[j] = ((sh_part[j] + sh_part[j + 64]) +
                        (sh_part[j + 128] + sh_part[j + 192])) + b2[j];
        out[(size_t)b * NUM_EXPERTS + j] = 0.0f;   // d_out poisoned; zero first
    }
    __syncthreads();

    // top-8 + softmax + scatter (strict '>' = first-index tie-break, as
    // jax.lax.top_k)
    if (j == 0) {
        int   idx[TOP_K];
        float val[TOP_K];
        unsigned long long used = 0ull;
        for (int k = 0; k < TOP_K; k++) {
            float best = -INFINITY;
            int bi = 0;
            for (int e = 0; e < NUM_EXPERTS; e++) {
                if (!((used >> e) & 1ull) && sh_logits[e] > best) {
                    best = sh_logits[e]; bi = e;
                }
            }
            used |= (1ull << bi);
            idx[k] = bi;
            val[k] = best;
        }
        float mx = val[0];
        float denom = 0.f;
        float ex[TOP_K];
        for (int k = 0; k < TOP_K; k++) { ex[k] = expf(val[k] - mx); denom += ex[k]; }
        float rden = 1.0f / denom;
        for (int k = 0; k < TOP_K; k++)
            out[(size_t)b * NUM_EXPERTS + idx[k]] = ex[k] * rden;
    }
}

// ---------------------------------------------------------------------------
extern "C" void kernel_launch(void* const* d_in, const int* in_sizes, int n_in,
                              void* d_out, int out_size) {
    const float* hs   = (const float*)d_in[0];
    const float* W1   = (const float*)d_in[1];
    const float* b1   = (const float*)d_in[2];
    const float* ln_g = (const float*)d_in[3];
    const float* ln_b = (const float*)d_in[4];
    const float* W2   = (const float*)d_in[5];
    const float* b2   = (const float*)d_in[6];
    // d_in[7] = top_k (hardcoded 8)

    float* out = (float*)d_out;

    pool_partial<<<BATCH * NSPLIT, 512>>>(hs);
    gemv1_partial<<<BATCH * KB, ROUTE_H>>>(W1);
    finale<<<BATCH, ROUTE_H>>>(b1, ln_g, ln_b, W2, b2, out);
}

// round 7
// speedup vs baseline: 1.0347x; 1.0258x over previous
#include <cuda_runtime.h>
#include <math.h>

#define BATCH 32
#define SEQ 4096
#define HIDDEN 2048
#define ROUTE_H 256
#define NUM_EXPERTS 64
#define TOP_K 8
#define LN_EPS 1e-5f

#define NSPLIT 16
#define SCHUNK (SEQ / NSPLIT)        // 256 rows per pool block
#define H4 (HIDDEN / 4)              // 512 float4 columns

#define KB 16                        // K-split blocks for GEMV1
#define KCHUNK (HIDDEN / KB)         // 128 hidden cols per GEMV1 block

// Scratch (no cudaMalloc allowed)
__device__ float g_partial[NSPLIT * BATCH * HIDDEN];   // [sp][b][h] = 4 MB
__device__ float g_hpart[KB * BATCH * ROUTE_H];        // [ks][b][j] = 512 KB
__device__ unsigned int g_cnt[BATCH];                  // per-batch election

// ---------------------------------------------------------------------------
// Kernel 1: partial mean-pool. grid = BATCH*NSPLIT = 512 blocks, 512 threads
// (single resident wave: 148 SMs x 4 blocks). Each thread accumulates one
// float4 column over its 256-row seq slice. __ldcs keeps the 1 GB one-touch
// stream from thrashing L2. Block 0 also resets the election counters
// (stream-ordered before kernel 2, so graph-replay safe).
// ---------------------------------------------------------------------------
__global__ void __launch_bounds__(512) pool_partial(const float* __restrict__ x) {
    int blk = blockIdx.x;
    int b   = blk / NSPLIT;
    int sp  = blk % NSPLIT;
    int c4  = threadIdx.x;  // 0..511

    if (blk == 0 && c4 < BATCH) g_cnt[c4] = 0u;

    const float4* base = (const float4*)(x) +
        ((size_t)b * SEQ + (size_t)sp * SCHUNK) * (size_t)H4 + c4;

    float4 acc = make_float4(0.f, 0.f, 0.f, 0.f);
#pragma unroll 8
    for (int s = 0; s < SCHUNK; s++) {
        float4 v = __ldcs(&base[(size_t)s * H4]);
        acc.x += v.x; acc.y += v.y; acc.z += v.z; acc.w += v.w;
    }

    float4* out = (float4*)(g_partial + ((size_t)sp * BATCH + b) * HIDDEN);
    out[c4] = acc;
}

// ---------------------------------------------------------------------------
// Kernel 2: GEMV1 K-split (grid = BATCH*KB = 512 blocks, 256 threads) with the
// per-batch finale fused in via last-block election. Block (b, ks) folds
// pooled cols [ks*128, ks*128+128), computes its 128-row GEMV1 slice, then the
// 16th finisher for batch b runs LN + GELU + GEMV2 + top-8 inline.
// Finale fold order is fixed -> deterministic output.
// ---------------------------------------------------------------------------
__global__ void __launch_bounds__(ROUTE_H) gemv1_finale(
    const float* __restrict__ W1, const float* __restrict__ b1,
    const float* __restrict__ ln_g, const float* __restrict__ ln_b,
    const float* __restrict__ W2, const float* __restrict__ b2,
    float* __restrict__ out)
{
    __shared__ float sh_pool[KCHUNK];
    __shared__ unsigned int s_elect;

    int blk = blockIdx.x;
    int b   = blk / KB;
    int ks  = blk % KB;
    int j   = threadIdx.x;           // 0..255
    int i0  = ks * KCHUNK;

    // Fold NSPLIT partials for this block's 128 pooled columns.
    if (j < KCHUNK) {
        float s = 0.f;
#pragma unroll
        for (int sp = 0; sp < NSPLIT; sp++)
            s += g_partial[((size_t)sp * BATCH + b) * HIDDEN + i0 + j];
        sh_pool[j] = s * (1.0f / SEQ);
    }
    __syncthreads();

    // Partial GEMV over 128 rows (coalesced W1 reads across j).
    float a0 = 0.f, a1 = 0.f, a2 = 0.f, a3 = 0.f;
    float a4 = 0.f, a5 = 0.f, a6 = 0.f, a7 = 0.f;
#pragma unroll 4
    for (int r = 0; r < KCHUNK; r += 8) {
        const float* w = W1 + (size_t)(i0 + r) * ROUTE_H + j;
        a0 += sh_pool[r + 0] * w[0 * ROUTE_H];
        a1 += sh_pool[r + 1] * w[1 * ROUTE_H];
        a2 += sh_pool[r + 2] * w[2 * ROUTE_H];
        a3 += sh_pool[r + 3] * w[3 * ROUTE_H];
        a4 += sh_pool[r + 4] * w[4 * ROUTE_H];
        a5 += sh_pool[r + 5] * w[5 * ROUTE_H];
        a6 += sh_pool[r + 6] * w[6 * ROUTE_H];
        a7 += sh_pool[r + 7] * w[7 * ROUTE_H];
    }
    g_hpart[((size_t)ks * BATCH + b) * ROUTE_H + j] =
        ((a0 + a1) + (a2 + a3)) + ((a4 + a5) + (a6 + a7));

    // ---- election: last finishing block of this batch runs the finale ----
    __threadfence();   // publish g_hpart slice before counting
    if (j == 0) {
        unsigned int old = atomicAdd(&g_cnt[b], 1u);
        s_elect = (old == KB - 1) ? 1u : 0u;
    }
    __syncthreads();
    if (!s_elect) return;
    __threadfence();   // acquire: all 16 slices now visible

    // =================== finale for batch b (256 threads) ===================
    __shared__ float sh_h[ROUTE_H];
    __shared__ float sh_w1r[8], sh_w2r[8];
    __shared__ float sh_part[ROUTE_H];
    __shared__ float sh_logits[NUM_EXPERTS];

    int lane = j & 31;
    int warp = j >> 5;

    float h = 0.f;
#pragma unroll
    for (int k = 0; k < KB; k++)
        h += g_hpart[((size_t)k * BATCH + b) * ROUTE_H + j];
    h += b1[j];

    // LN reduce via warp shuffles (8 warps)
    float s1 = h, s2 = h * h;
#pragma unroll
    for (int o = 16; o > 0; o >>= 1) {
        s1 += __shfl_xor_sync(0xffffffffu, s1, o);
        s2 += __shfl_xor_sync(0xffffffffu, s2, o);
    }
    if (lane == 0) { sh_w1r[warp] = s1; sh_w2r[warp] = s2; }
    __syncthreads();
    float t1 = sh_w1r[lane & 7], t2 = sh_w2r[lane & 7];
#pragma unroll
    for (int o = 4; o > 0; o >>= 1) {
        t1 += __shfl_xor_sync(0xffffffffu, t1, o);
        t2 += __shfl_xor_sync(0xffffffffu, t2, o);
    }
    t1 = __shfl_sync(0xffffffffu, t1, 0);
    t2 = __shfl_sync(0xffffffffu, t2, 0);

    float mu  = t1 * (1.0f / ROUTE_H);
    float ms  = t2 * (1.0f / ROUTE_H);
    float inv = rsqrtf(ms - mu * mu + LN_EPS);
    h = (h - mu) * inv * ln_g[j] + ln_b[j];
    h = 0.5f * h * (1.0f + erff(h * 0.70710678118654752f));   // exact GELU
    sh_h[j] = h;
    __syncthreads();

    // GEMV2, K-split 4 within the block: 256 threads = 64 experts x 4 slices
    {
        int e   = j & (NUM_EXPERTS - 1);
        int ks2 = j >> 6;
        int r0  = ks2 * (ROUTE_H / 4);
        float a = 0.f;
#pragma unroll 8
        for (int i = 0; i < ROUTE_H / 4; i++)
            a += sh_h[r0 + i] * W2[(size_t)(r0 + i) * NUM_EXPERTS + e];
        sh_part[j] = a;
    }
    __syncthreads();
    if (j < NUM_EXPERTS) {
        sh_logits[j] = ((sh_part[j] + sh_part[j + 64]) +
                        (sh_part[j + 128] + sh_part[j + 192])) + b2[j];
        out[(size_t)b * NUM_EXPERTS + j] = 0.0f;   // d_out poisoned; zero first
    }
    __syncthreads();

    // top-8 + softmax + scatter (strict '>' = first-index tie-break, matching
    // jax.lax.top_k)
    if (j == 0) {
        int   idx[TOP_K];
        float val[TOP_K];
        unsigned long long used = 0ull;
        for (int k = 0; k < TOP_K; k++) {
            float best = -INFINITY;
            int bi = 0;
            for (int e = 0; e < NUM_EXPERTS; e++) {
                if (!((used >> e) & 1ull) && sh_logits[e] > best) {
                    best = sh_logits[e]; bi = e;
                }
            }
            used |= (1ull << bi);
            idx[k] = bi;
            val[k] = best;
        }
        float mx = val[0];
        float denom = 0.f;
        float ex[TOP_K];
        for (int k = 0; k < TOP_K; k++) { ex[k] = expf(val[k] - mx); denom += ex[k]; }
        float rden = 1.0f / denom;
        for (int k = 0; k < TOP_K; k++)
            out[(size_t)b * NUM_EXPERTS + idx[k]] = ex[k] * rden;
    }
}

// ---------------------------------------------------------------------------
extern "C" void kernel_launch(void* const* d_in, const int* in_sizes, int n_in,
                              void* d_out, int out_size) {
    const float* hs   = (const float*)d_in[0];
    const float* W1   = (const float*)d_in[1];
    const float* b1   = (const float*)d_in[2];
    const float* ln_g = (const float*)d_in[3];
    const float* ln_b = (const float*)d_in[4];
    const float* W2   = (const float*)d_in[5];
    const float* b2   = (const float*)d_in[6];
    // d_in[7] = top_k (hardcoded 8)

    float* out = (float*)d_out;

    pool_partial<<<BATCH * NSPLIT, 512>>>(hs);
    gemv1_finale<<<BATCH * KB, ROUTE_H>>>(W1, b1, ln_g, ln_b, W2, b2, out);
}